// round 1
// baseline (speedup 1.0000x reference)
#include <cuda_runtime.h>
#include <cuda_bf16.h>

// Problem: stable counting-sort of 8.4M rows by 4-class label, margin-adjust
// the true-class logit, emit (sorted data [N,4], sorted labels as float [N],
// scalar mean-NLL loss). Output buffer: [data | labels | loss] as float32.

constexpr int TPB = 256;
constexpr int ROWS_PER_THREAD = 16;
constexpr int ROWS_PER_BLOCK = TPB * ROWS_PER_THREAD;   // 4096
constexpr int NW = TPB / 32;                            // 8 warps
constexpr int MAX_BLOCKS = 8192;

__device__ int4 g_blockHist[MAX_BLOCKS];
__device__ int4 g_blockOffset[MAX_BLOCKS];
__device__ double g_loss;

static __device__ __forceinline__ int4 add4(int4 a, int4 b) {
    return make_int4(a.x + b.x, a.y + b.y, a.z + b.z, a.w + b.w);
}

// ---------------------------------------------------------------------------
// Pass 1: per-block label histograms (register counters, no atomics)
// ---------------------------------------------------------------------------
__global__ void __launch_bounds__(TPB) histKernel(const int* __restrict__ label, int n) {
    int tid = threadIdx.x;
    int base = blockIdx.x * ROWS_PER_BLOCK;
    int c0 = 0, c1 = 0, c2 = 0, c3 = 0;
#pragma unroll
    for (int it = 0; it < ROWS_PER_THREAD; ++it) {
        int idx = base + it * TPB + tid;
        if (idx < n) {
            int c = label[idx];
            c0 += (c == 0); c1 += (c == 1); c2 += (c == 2); c3 += (c == 3);
        }
    }
    // warp reduce
#pragma unroll
    for (int off = 16; off > 0; off >>= 1) {
        c0 += __shfl_down_sync(0xffffffffu, c0, off);
        c1 += __shfl_down_sync(0xffffffffu, c1, off);
        c2 += __shfl_down_sync(0xffffffffu, c2, off);
        c3 += __shfl_down_sync(0xffffffffu, c3, off);
    }
    __shared__ int sh[4];
    if (tid < 4) sh[tid] = 0;
    __syncthreads();
    if ((tid & 31) == 0) {
        atomicAdd(&sh[0], c0); atomicAdd(&sh[1], c1);
        atomicAdd(&sh[2], c2); atomicAdd(&sh[3], c3);
    }
    __syncthreads();
    if (tid == 0)
        g_blockHist[blockIdx.x] = make_int4(sh[0], sh[1], sh[2], sh[3]);
}

// ---------------------------------------------------------------------------
// Pass 2: single-block exclusive scan of per-block histograms (per class),
// plus class base offsets; also zeroes the loss accumulator.
// ---------------------------------------------------------------------------
__global__ void __launch_bounds__(TPB) scanKernel(int numBlocks) {
    __shared__ int4 sh[TPB];
    int tid = threadIdx.x;
    int chunk = (numBlocks + TPB - 1) / TPB;
    int start = tid * chunk;
    int end = min(start + chunk, numBlocks);

    int4 s = make_int4(0, 0, 0, 0);
    for (int j = start; j < end; ++j) s = add4(s, g_blockHist[j]);

    sh[tid] = s;
    __syncthreads();
    // Hillis-Steele inclusive scan across threads
    for (int off = 1; off < TPB; off <<= 1) {
        int4 v = sh[tid];
        if (tid >= off) v = add4(v, sh[tid - off]);
        __syncthreads();
        sh[tid] = v;
        __syncthreads();
    }
    int4 incl = sh[tid];
    int4 tot = sh[TPB - 1];
    int4 excl = make_int4(incl.x - s.x, incl.y - s.y, incl.z - s.z, incl.w - s.w);

    // class bases: class c starts after totals of classes < c
    int4 run;
    run.x = excl.x;
    run.y = excl.y + tot.x;
    run.z = excl.z + tot.x + tot.y;
    run.w = excl.w + tot.x + tot.y + tot.z;

    for (int j = start; j < end; ++j) {
        int4 h = g_blockHist[j];
        g_blockOffset[j] = run;
        run = add4(run, h);
    }
    if (tid == 0) g_loss = 0.0;
}

// ---------------------------------------------------------------------------
// Pass 3: stable rank within block via warp ballots, margin-adjust, scatter,
// fused loss accumulation.
// ---------------------------------------------------------------------------
__global__ void __launch_bounds__(TPB) scatterKernel(const float* __restrict__ data,
                                                    const int* __restrict__ label,
                                                    float* __restrict__ outData,
                                                    float* __restrict__ outLabel,
                                                    int n) {
    __shared__ int warpTot[NW][4];
    __shared__ int running[4];
    __shared__ int blockOff[4];
    __shared__ float warpLoss[NW];

    int tid = threadIdx.x;
    int w = tid >> 5;
    int lane = tid & 31;
    unsigned laneLT = (1u << lane) - 1u;

    if (tid < 4) {
        const int* bo = reinterpret_cast<const int*>(g_blockOffset);
        blockOff[tid] = bo[blockIdx.x * 4 + tid];
        running[tid] = 0;
    }
    __syncthreads();

    int base = blockIdx.x * ROWS_PER_BLOCK;
    float lsum = 0.0f;

#pragma unroll
    for (int it = 0; it < ROWS_PER_THREAD; ++it) {
        int idx = base + it * TPB + tid;
        bool valid = idx < n;
        int c = valid ? label[idx] : 4;

        unsigned m0 = __ballot_sync(0xffffffffu, c == 0);
        unsigned m1 = __ballot_sync(0xffffffffu, c == 1);
        unsigned m2 = __ballot_sync(0xffffffffu, c == 2);
        unsigned m3 = __ballot_sync(0xffffffffu, c == 3);
        if (lane == 0) {
            warpTot[w][0] = __popc(m0);
            warpTot[w][1] = __popc(m1);
            warpTot[w][2] = __popc(m2);
            warpTot[w][3] = __popc(m3);
        }
        unsigned myM = (c == 0) ? m0 : (c == 1) ? m1 : (c == 2) ? m2 : m3;
        int wr = __popc(myM & laneLT);
        __syncthreads();

        if (valid) {
            int pre = 0;
            for (int ww = 0; ww < w; ++ww) pre += warpTot[ww][c];
            int dest = blockOff[c] + running[c] + pre + wr;

            float4 r = reinterpret_cast<const float4*>(data)[idx];
            float v = (c == 0) ? r.x : (c == 1) ? r.y : (c == 2) ? r.z : r.w;
            float adj = (v > 0.0f) ? v * (1.0f / 4.00001f) - 0.5f
                                   : v * 4.00001f - 0.5f;
            if (c == 0) r.x = adj; else if (c == 1) r.y = adj;
            else if (c == 2) r.z = adj; else r.w = adj;

            float mx = fmaxf(fmaxf(r.x, r.y), fmaxf(r.z, r.w));
            float lse = mx + logf(expf(r.x - mx) + expf(r.y - mx) +
                                  expf(r.z - mx) + expf(r.w - mx));
            lsum += lse - adj;   // -log p[true]

            reinterpret_cast<float4*>(outData)[dest] = r;
            outLabel[dest] = (float)c;
        }
        __syncthreads();
        if (tid < 4) {
            int s = 0;
#pragma unroll
            for (int ww = 0; ww < NW; ++ww) s += warpTot[ww][tid];
            running[tid] += s;
        }
        __syncthreads();
    }

    // loss reduction: warp shuffle -> shared -> one double atomic per block
#pragma unroll
    for (int off = 16; off > 0; off >>= 1)
        lsum += __shfl_down_sync(0xffffffffu, lsum, off);
    if (lane == 0) warpLoss[w] = lsum;
    __syncthreads();
    if (tid == 0) {
        double s = 0.0;
#pragma unroll
        for (int ww = 0; ww < NW; ++ww) s += (double)warpLoss[ww];
        atomicAdd(&g_loss, s);
    }
}

__global__ void finishKernel(float* __restrict__ out, int n) {
    out[(size_t)n * 5] = (float)(g_loss / (double)n);
}

extern "C" void kernel_launch(void* const* d_in, const int* in_sizes, int n_in,
                              void* d_out, int out_size) {
    const float* data = (const float*)d_in[0];
    const int* label = (const int*)d_in[1];
    float* out = (float*)d_out;
    int n = in_sizes[1];

    int nb = (n + ROWS_PER_BLOCK - 1) / ROWS_PER_BLOCK;

    histKernel<<<nb, TPB>>>(label, n);
    scanKernel<<<1, TPB>>>(nb);
    scatterKernel<<<nb, TPB>>>(data, label, out, out + (size_t)n * 4, n);
    finishKernel<<<1, 1>>>(out, n);
}